// round 3
// baseline (speedup 1.0000x reference)
#include <cuda_runtime.h>
#include <math.h>

#define GRP 64
#define MN  128
#define NNODES (GRP*MN)

typedef unsigned long long u64;

__device__ __forceinline__ u64 pk(float lo, float hi) {
    u64 r; asm("mov.b64 %0, {%1,%2};" : "=l"(r) : "f"(lo), "f"(hi)); return r;
}
__device__ __forceinline__ void upk(float& lo, float& hi, u64 v) {
    asm("mov.b64 {%0,%1}, %2;" : "=f"(lo), "=f"(hi) : "l"(v));
}
__device__ __forceinline__ u64 f2mul(u64 a, u64 b) {
    u64 r; asm("mul.rn.f32x2 %0,%1,%2;" : "=l"(r) : "l"(a), "l"(b)); return r;
}
__device__ __forceinline__ u64 f2add(u64 a, u64 b) {
    u64 r; asm("add.rn.f32x2 %0,%1,%2;" : "=l"(r) : "l"(a), "l"(b)); return r;
}
__device__ __forceinline__ u64 f2fma(u64 a, u64 b, u64 c) {
    u64 r; asm("fma.rn.f32x2 %0,%1,%2,%3;" : "=l"(r) : "l"(a), "l"(b), "l"(c)); return r;
}
__device__ __forceinline__ float ex2f(float x) {
    float r; asm("ex2.approx.f32 %0, %1;" : "=f"(r) : "f"(x)); return r;
}
__device__ __forceinline__ float rcpf(float x) {
    float r; asm("rcp.approx.f32 %0, %1;" : "=f"(r) : "f"(x)); return r;
}
__device__ __forceinline__ float rsqf(float x) {
    float r; asm("rsqrt.approx.f32 %0, %1;" : "=f"(r) : "f"(x)); return r;
}

__global__ __launch_bounds__(256, 3)
void rsaef_kernel(const float* __restrict__ sf,   // (N,4)
                  const float* __restrict__ pos,  // (N,3)
                  float* __restrict__ out)
{
    __shared__ alignas(8) float s_npx[MN];
    __shared__ alignas(8) float s_npy[MN];
    __shared__ alignas(8) float s_npz[MN];
    __shared__ alignas(8) float s_q  [MN];
    __shared__ alignas(8) float s_nmx[MN];
    __shared__ alignas(8) float s_nmy[MN];
    __shared__ alignas(8) float s_nmz[MN];
    __shared__ float red[MN][9];  // padded: stride 9 words -> conflict-free

    const int g    = blockIdx.x;
    const int c    = blockIdx.y;      // radial chunk: radials 2c, 2c+1
    const int tid  = threadIdx.x;
    const int i    = tid & (MN - 1);
    const int half = tid >> 7;

    if (tid < MN) {
        const float* p = pos + (size_t)(g * MN + tid) * 3;
        const float* f = sf  + (size_t)(g * MN + tid) * 4;
        s_npx[tid] = -p[0]; s_npy[tid] = -p[1]; s_npz[tid] = -p[2];
        s_q[tid]   =  f[0];
        s_nmx[tid] = -f[3]; s_nmy[tid] = -f[1]; s_nmz[tid] = -f[2];
    }
    __syncthreads();

    // radial constants in double (matches numpy f64 -> f32)
    const double PI  = 3.14159265358979323846;
    const double KCd = 14.399645351950548;
    const double INV_SQRT_PI_D = 0.5641895835477562869480794515607725858;
    const float  SQL2E = 1.2011224087864498f;   // sqrt(log2 e)
    float l0fv[2], l1wv[2], si0c[2], si1c[2], ginvf[2];
    u64 HW[2], HWL[2], GI[2], IW2[2];
    #pragma unroll
    for (int t = 0; t < 2; t++) {
        int k = 2 * c + t;
        double sig = 0.5 + (double)k * (2.5 / 15.0);
        double w   = sqrt((1.0 + sig * sig) * 0.5);
        double pi15 = pow(PI, 1.5);
        double s3 = sig * sig * sig;
        double s5 = s3 * sig * sig;
        double cl0rec  = 1.0 / sqrt(pi15 * s3);
        double cl0mult = 1.0 / (pow(2.0 * PI, 1.5) * s3);
        double cl1rec  = 1.0 / sqrt(pi15 * s5 * 3.0 / 2.0);
        double L0F = cl0rec / cl0mult;
        double L1W = sqrt(3.0) * sig * sig * cl1rec / cl0mult;
        float hw   = (float)(0.5 / w);
        float gi   = (float)(INV_SQRT_PI_D / w);
        float iw2  = (float)(1.0 / (2.0 * w * w));
        l0fv[t] = (float)(KCd * L0F);
        l1wv[t] = (float)(KCd * L1W);
        si0c[t] = (float)(KCd * L0F * INV_SQRT_PI_D / w);
        si1c[t] = (float)(KCd * L1W / (6.0 * w * w * w) * INV_SQRT_PI_D);
        ginvf[t] = gi;
        HW[t]  = pk(hw, hw);
        HWL[t] = pk(hw * SQL2E, hw * SQL2E);
        GI[t]  = pk(gi, gi);
        IW2[t] = pk(iw2, iw2);
    }
    (void)ginvf;

    const u64 ONE   = pk(1.f, 1.f);
    const u64 NEG1  = pk(-1.f, -1.f);
    const u64 THREE = pk(3.f, 3.f);
    const u64 PC    = pk(0.3275911f, 0.3275911f);
    const u64 A5    = pk(1.061405429f, 1.061405429f);
    const u64 A4    = pk(-1.453152027f, -1.453152027f);
    const u64 A3    = pk(1.421413741f, 1.421413741f);
    const u64 A2    = pk(-0.284496736f, -0.284496736f);
    const u64 A1    = pk(0.254829592f, 0.254829592f);

    const float mex = -s_npx[i], mey = -s_npy[i], mez = -s_npz[i];
    const u64 MEX = pk(mex, mex), MEY = pk(mey, mey), MEZ = pk(mez, mez);

    u64 acc0[2] = {0, 0}, ax[2] = {0, 0}, ay[2] = {0, 0}, az[2] = {0, 0};

    const int jbase = half * 32;
    #pragma unroll 2
    for (int qq = 0; qq < 32; qq++) {
        const int jj = jbase + qq;
        const u64 npx2 = *(const u64*)&s_npx[2 * jj];
        const u64 npy2 = *(const u64*)&s_npy[2 * jj];
        const u64 npz2 = *(const u64*)&s_npz[2 * jj];
        const u64 q2   = *(const u64*)&s_q  [2 * jj];
        const u64 nmx2 = *(const u64*)&s_nmx[2 * jj];
        const u64 nmy2 = *(const u64*)&s_nmy[2 * jj];
        const u64 nmz2 = *(const u64*)&s_nmz[2 * jj];

        const u64 Rx2 = f2add(MEX, npx2);
        const u64 Ry2 = f2add(MEY, npy2);
        const u64 Rz2 = f2add(MEZ, npz2);
        const u64 r22 = f2fma(Rx2, Rx2, f2fma(Ry2, Ry2, f2mul(Rz2, Rz2)));

        float ra, rb;
        upk(ra, rb, r22);
        ra = fmaxf(ra, 1e-20f); rb = fmaxf(rb, 1e-20f);
        const float ia = rsqf(ra), ib = rsqf(rb);
        const u64 invr2 = pk(ia, ib);
        const u64 r2c   = pk(ra, rb);
        const u64 rv2   = f2mul(r2c, invr2);            // r per half

        const u64 hx2 = f2mul(Rx2, invr2);
        const u64 hy2 = f2mul(Ry2, invr2);
        const u64 hz2 = f2mul(Rz2, invr2);
        const u64 s2  = f2fma(nmx2, hx2, f2fma(nmy2, hy2, f2mul(nmz2, hz2))); // -muR
        const u64 muR2 = f2mul(s2, NEG1);

        const float ml = (2 * jj     == i) ? 0.f : 1.f;
        const float mh = (2 * jj + 1 == i) ? 0.f : 1.f;
        const u64 mk2 = pk(ml, mh);

        #pragma unroll
        for (int t = 0; t < 2; t++) {
            const u64 u2   = f2mul(rv2, HW[t]);
            const u64 ul2  = f2mul(rv2, HWL[t]);
            const u64 nul2 = f2mul(ul2, NEG1);
            const u64 nsq  = f2mul(ul2, nul2);
            float x0, x1;
            upk(x0, x1, nsq);
            const u64 e2 = pk(ex2f(x0), ex2f(x1));       // exp(-u^2)

            const u64 d2 = f2fma(u2, PC, ONE);
            float d0, d1;
            upk(d0, d1, d2);
            const u64 tt = pk(rcpf(d0), rcpf(d1));

            u64 P = f2fma(A5, tt, A4);
            P = f2fma(P, tt, A3);
            P = f2fma(P, tt, A2);
            P = f2fma(P, tt, A1);
            const u64 pr   = f2mul(f2mul(P, tt), e2);
            const u64 erfu = f2fma(pr, NEG1, ONE);

            u64 T = f2mul(erfu, invr2);
            T = f2mul(T, mk2);
            const u64 gg = f2mul(e2, GI[t]);
            const u64 fp = f2mul(f2fma(T, NEG1, gg), invr2);
            u64 fpor = f2mul(fp, invr2);
            fpor = f2mul(fpor, mk2);

            const u64 coef = f2mul(f2fma(gg, IW2[t], f2mul(fpor, THREE)), muR2);
            const u64 A = f2fma(fp, q2, coef);

            acc0[t] = f2fma(T, q2, acc0[t]);
            acc0[t] = f2fma(fp, s2, acc0[t]);
            ax[t] = f2fma(A, hx2, ax[t]);
            ax[t] = f2fma(fpor, nmx2, ax[t]);
            ay[t] = f2fma(A, hy2, ay[t]);
            ay[t] = f2fma(fpor, nmy2, ay[t]);
            az[t] = f2fma(A, hz2, az[t]);
            az[t] = f2fma(fpor, nmz2, az[t]);
        }
    }

    // horizontal sum of the two packed halves
    float r0[8];
    #pragma unroll
    for (int t = 0; t < 2; t++) {
        float lo, hi;
        upk(lo, hi, acc0[t]); r0[t * 4 + 0] = lo + hi;
        upk(lo, hi, ax[t]);   r0[t * 4 + 1] = lo + hi;
        upk(lo, hi, ay[t]);   r0[t * 4 + 2] = lo + hi;
        upk(lo, hi, az[t]);   r0[t * 4 + 3] = lo + hi;
    }

    if (half == 1) {
        #pragma unroll
        for (int m = 0; m < 8; m++) red[i][m] = r0[m];
    }
    __syncthreads();

    const int node = g * MN + i;
    if (half == 0) {
        float* frow = out + (size_t)node * 64;
        #pragma unroll
        for (int t = 0; t < 2; t++) {
            const int k = 2 * c + t;
            const float v0 = r0[t * 4 + 0] + red[i][t * 4 + 0];
            const float vx = r0[t * 4 + 1] + red[i][t * 4 + 1];
            const float vy = r0[t * 4 + 2] + red[i][t * 4 + 2];
            const float vz = r0[t * 4 + 3] + red[i][t * 4 + 3];
            frow[k]              = l0fv[t] * v0;
            frow[16 + 3 * k + 0] = l1wv[t] * vy;   // component 1
            frow[16 + 3 * k + 1] = l1wv[t] * vz;   // component 2
            frow[16 + 3 * k + 2] = l1wv[t] * vx;   // component 0
        }
    } else {
        // self-interaction terms (no reduction needed)
        float* srow = out + (size_t)NNODES * 64 + (size_t)node * 64;
        const float q  =  s_q[i];
        const float m1 = -s_nmy[i];   // sf[:,1]
        const float m2 = -s_nmz[i];   // sf[:,2]
        const float m3 = -s_nmx[i];   // sf[:,3]
        #pragma unroll
        for (int t = 0; t < 2; t++) {
            const int k = 2 * c + t;
            srow[k]              = si0c[t] * q;
            srow[16 + 3 * k + 0] = si1c[t] * m1;
            srow[16 + 3 * k + 1] = si1c[t] * m2;
            srow[16 + 3 * k + 2] = si1c[t] * m3;
        }
    }
}

extern "C" void kernel_launch(void* const* d_in, const int* in_sizes, int n_in,
                              void* d_out, int out_size)
{
    const float* sf  = (const float*)d_in[0];
    const float* pos = (const float*)d_in[1];
    float* out = (float*)d_out;

    dim3 grid(GRP, 8);
    rsaef_kernel<<<grid, 256>>>(sf, pos, out);
}